// round 1
// baseline (speedup 1.0000x reference)
#include <cuda_runtime.h>
#include <cuda_bf16.h>
#include <math.h>

// Problem constants (fixed shapes from reference setup_inputs)
#define NROWS 8192      // b*n = 64*128
#define CDIM  256       // feature dim
#define NLAB  128       // labels = i % 128
#define BQ    64        // b
#define DDIM  65536     // b*d = 64*1024
#define MARGIN 0.3f

// GEMM tiling
#define BM 128
#define BN 128
#define BK 16
#define TM 8
#define TN 8
#define NTHREADS 256
#define JCHUNKS 16
#define JT_PER_CHUNK (NROWS / BN / JCHUNKS)   // 64/16 = 4

// Scratch (device globals; no allocation allowed)
__device__ float g_sq[NROWS];
__device__ float g_hp2[NROWS];   // max squared dist over positives (nonneg)
__device__ float g_hn2[NROWS];   // min squared dist over negatives (nonneg)

// ---------------------------------------------------------------------------
// Kernel 1: per-row squared norms + reset hp2/hn2. One warp per row.
// grid: 1024 blocks x 256 threads (8 warps) => 8192 warps = 8192 rows.
// ---------------------------------------------------------------------------
__global__ void init_kernel(const float* __restrict__ x) {
    int warp = (blockIdx.x * blockDim.x + threadIdx.x) >> 5;
    int lane = threadIdx.x & 31;
    if (warp >= NROWS) return;
    const float4* xr = reinterpret_cast<const float4*>(x + (size_t)warp * CDIM);
    // 256 floats = 64 float4 per row; each lane reads 2
    float4 v0 = xr[lane * 2 + 0];
    float4 v1 = xr[lane * 2 + 1];
    float s = v0.x * v0.x + v0.y * v0.y + v0.z * v0.z + v0.w * v0.w
            + v1.x * v1.x + v1.y * v1.y + v1.z * v1.z + v1.w * v1.w;
#pragma unroll
    for (int off = 16; off > 0; off >>= 1)
        s += __shfl_xor_sync(0xFFFFFFFFu, s, off);
    if (lane == 0) {
        g_sq[warp]  = s;
        g_hp2[warp] = 0.0f;                      // bits 0x00000000
        g_hn2[warp] = __int_as_float(0x7F7FFFFF); // FLT_MAX
    }
}

// ---------------------------------------------------------------------------
// Kernel 2: fused Gram + hardest-pos/neg mining on SQUARED distances.
// Block computes a BM x BN tile per j-tile; each block owns one i-tile and
// JT_PER_CHUNK j-tiles; partial hp2/hn2 merged via float-as-int atomics
// (valid: all values nonnegative).
// ---------------------------------------------------------------------------
__global__ void __launch_bounds__(NTHREADS, 1)
pair_kernel(const float* __restrict__ x) {
    __shared__ float As[BK][BM + 4];
    __shared__ float Bs[BK][BN + 4];

    const int tid = threadIdx.x;
    const int tx = tid & 15;        // 0..15, column group
    const int ty = tid >> 4;        // 0..15, row group
    const int iBase = blockIdx.x * BM;
    const int jt0 = blockIdx.y * JT_PER_CHUNK;

    float hp2[TM], hn2[TM], sqi[TM];
#pragma unroll
    for (int m = 0; m < TM; m++) {
        hp2[m] = 0.0f;
        hn2[m] = __int_as_float(0x7F7FFFFF);
        sqi[m] = g_sq[iBase + ty * TM + m];
    }

    // Global-load thread mapping: 2048 floats per tile per k-chunk,
    // thread loads 2 float4s (rows lr and lr+64, k-offset lk..lk+3).
    const int lr = tid >> 2;         // 0..63
    const int lk = (tid & 3) * 4;    // 0,4,8,12

    for (int jt = jt0; jt < jt0 + JT_PER_CHUNK; jt++) {
        const int jBase = jt * BN;
        float acc[TM][TN];
#pragma unroll
        for (int m = 0; m < TM; m++)
#pragma unroll
            for (int n = 0; n < TN; n++) acc[m][n] = 0.0f;

        for (int k0 = 0; k0 < CDIM; k0 += BK) {
            float4 a0 = *reinterpret_cast<const float4*>(&x[(size_t)(iBase + lr)       * CDIM + k0 + lk]);
            float4 a1 = *reinterpret_cast<const float4*>(&x[(size_t)(iBase + lr + 64)  * CDIM + k0 + lk]);
            float4 b0 = *reinterpret_cast<const float4*>(&x[(size_t)(jBase + lr)       * CDIM + k0 + lk]);
            float4 b1 = *reinterpret_cast<const float4*>(&x[(size_t)(jBase + lr + 64)  * CDIM + k0 + lk]);
            As[lk + 0][lr] = a0.x; As[lk + 1][lr] = a0.y; As[lk + 2][lr] = a0.z; As[lk + 3][lr] = a0.w;
            As[lk + 0][lr + 64] = a1.x; As[lk + 1][lr + 64] = a1.y; As[lk + 2][lr + 64] = a1.z; As[lk + 3][lr + 64] = a1.w;
            Bs[lk + 0][lr] = b0.x; Bs[lk + 1][lr] = b0.y; Bs[lk + 2][lr] = b0.z; Bs[lk + 3][lr] = b0.w;
            Bs[lk + 0][lr + 64] = b1.x; Bs[lk + 1][lr + 64] = b1.y; Bs[lk + 2][lr + 64] = b1.z; Bs[lk + 3][lr + 64] = b1.w;
            __syncthreads();

#pragma unroll
            for (int k = 0; k < BK; k++) {
                float4 a0r = *reinterpret_cast<const float4*>(&As[k][ty * TM]);
                float4 a1r = *reinterpret_cast<const float4*>(&As[k][ty * TM + 4]);
                float4 b0r = *reinterpret_cast<const float4*>(&Bs[k][tx * TN]);
                float4 b1r = *reinterpret_cast<const float4*>(&Bs[k][tx * TN + 4]);
                float ar[TM] = {a0r.x, a0r.y, a0r.z, a0r.w, a1r.x, a1r.y, a1r.z, a1r.w};
                float br[TN] = {b0r.x, b0r.y, b0r.z, b0r.w, b1r.x, b1r.y, b1r.z, b1r.w};
#pragma unroll
                for (int m = 0; m < TM; m++)
#pragma unroll
                    for (int n = 0; n < TN; n++)
                        acc[m][n] = fmaf(ar[m], br[n], acc[m][n]);
            }
            __syncthreads();
        }

        // Epilogue: mine squared distances (sqrt deferred; monotone).
#pragma unroll
        for (int n = 0; n < TN; n++) {
            const int j = jBase + tx * TN + n;
            const float sqj = g_sq[j];
#pragma unroll
            for (int m = 0; m < TM; m++) {
                const int i = iBase + ty * TM + m;
                float d2 = fmaxf(sqi[m] - 2.0f * acc[m][n] + sqj, 0.0f);
                const bool same = ((i ^ j) & (NLAB - 1)) == 0;
                if (same) {
                    if (i != j) hp2[m] = fmaxf(hp2[m], d2);
                } else {
                    hn2[m] = fminf(hn2[m], d2);
                }
            }
        }
    }

    // Reduce across the 16 tx lanes (xor offsets stay inside the 16-lane half)
#pragma unroll
    for (int m = 0; m < TM; m++) {
#pragma unroll
        for (int off = 8; off > 0; off >>= 1) {
            hp2[m] = fmaxf(hp2[m], __shfl_xor_sync(0xFFFFFFFFu, hp2[m], off));
            hn2[m] = fminf(hn2[m], __shfl_xor_sync(0xFFFFFFFFu, hn2[m], off));
        }
        if (tx == 0) {
            const int row = iBase + ty * TM + m;
            atomicMax(reinterpret_cast<int*>(&g_hp2[row]), __float_as_int(hp2[m]));
            atomicMin(reinterpret_cast<int*>(&g_hn2[row]), __float_as_int(hn2[m]));
        }
    }
}

// ---------------------------------------------------------------------------
// Kernel 3: final scalar = dr + t_loss + mse. Single block, deterministic
// tree reduction.
// ---------------------------------------------------------------------------
__global__ void final_kernel(const float* __restrict__ gt,
                             const float* __restrict__ s0,
                             const float* __restrict__ s1,
                             const float* __restrict__ s2,
                             const float* __restrict__ e0,
                             const float* __restrict__ e1,
                             const float* __restrict__ l0,
                             const float* __restrict__ l1,
                             float* __restrict__ out) {
    __shared__ float red[NTHREADS];
    const int tid = threadIdx.x;

    float tsum = 0.0f;
    for (int i = tid; i < NROWS; i += NTHREADS) {
        float hp = sqrtf(g_hp2[i]);
        float hn = sqrtf(g_hn2[i]);
        tsum += fmaxf(hp - hn + MARGIN, 0.0f);
    }

    float msum = 0.0f;
    for (int i = tid; i < BQ; i += NTHREADS) {
        float g = gt[i];
        float a = s0[i] - g, b = s1[i] - g, c = s2[i] - g;
        msum += a * a + b * b + c * c;
    }

    float dsum = 0.0f;
    for (int i = tid; i < DDIM; i += NTHREADS) {
        dsum += fabsf(e0[i] - l0[i]) + fabsf(e1[i] - l1[i]);
    }

    // three sequential deterministic block reductions
    float vals[3] = {tsum, msum, dsum};
    float res[3];
#pragma unroll
    for (int v = 0; v < 3; v++) {
        red[tid] = vals[v];
        __syncthreads();
        for (int s = NTHREADS / 2; s > 0; s >>= 1) {
            if (tid < s) red[tid] += red[tid + s];
            __syncthreads();
        }
        res[v] = red[0];
        __syncthreads();
    }

    if (tid == 0) {
        float t_loss = res[0] / (float)NROWS;
        float mse    = res[1] / (float)(BQ * 3);
        float dr     = res[2] / (float)DDIM;
        out[0] = dr + t_loss + mse;
    }
}

// ---------------------------------------------------------------------------
extern "C" void kernel_launch(void* const* d_in, const int* in_sizes, int n_in,
                              void* d_out, int out_size) {
    const float* feat = (const float*)d_in[0];
    const float* gt   = (const float*)d_in[1];
    const float* s0   = (const float*)d_in[2];
    const float* s1   = (const float*)d_in[3];
    const float* s2   = (const float*)d_in[4];
    const float* e0   = (const float*)d_in[5];
    const float* e1   = (const float*)d_in[6];
    const float* l0   = (const float*)d_in[7];
    const float* l1   = (const float*)d_in[8];
    float* out = (float*)d_out;

    init_kernel<<<NROWS * 32 / NTHREADS, NTHREADS>>>(feat);
    dim3 grid(NROWS / BM, JCHUNKS);
    pair_kernel<<<grid, NTHREADS>>>(feat);
    final_kernel<<<1, NTHREADS>>>(gt, s0, s1, s2, e0, e1, l0, l1, out);
}

// round 2
// speedup vs baseline: 1.9508x; 1.9508x over previous
#include <cuda_runtime.h>
#include <cuda_bf16.h>
#include <math.h>

// Problem constants (fixed shapes from reference setup_inputs)
#define NROWS 8192      // b*n = 64*128
#define CDIM  256       // feature dim
#define NLAB  128       // labels = i % 128
#define BQ    64        // b
#define DDIM  65536     // b*d = 64*1024
#define MARGIN 0.3f
#define NTILES 64       // NROWS / 128
#define NPAIRTILES 2080 // NTILES*(NTILES+1)/2

// GEMM tiling
#define BM 128
#define BN 128
#define BK 16
#define TM 8
#define TN 8
#define NTHREADS 256

#define FLTMAX_BITS 0x7F7FFFFF

// Packed f32x2 helpers
#define FMA_F32X2(d, a, b, c) \
    asm("fma.rn.f32x2 %0, %1, %2, %3;" : "=l"(d) : "l"(a), "l"(b), "l"(c))
#define PACKDUP_F32X2(d, s) \
    asm("mov.b64 %0, {%1, %1};" : "=l"(d) : "f"(s))
#define UNPACK_F32X2(lo, hi, v) \
    asm("mov.b64 {%0, %1}, %2;" : "=f"(lo), "=f"(hi) : "l"(v))

// Scratch (device globals; no allocation allowed)
__device__ float g_sq[NROWS];
__device__ float g_hp2[NROWS];   // max squared dist over positives (nonneg)
__device__ float g_hn2[NROWS];   // min squared dist over negatives (nonneg)

// ---------------------------------------------------------------------------
// Kernel 1: per-row squared norms + reset hp2/hn2. One warp per row.
// ---------------------------------------------------------------------------
__global__ void init_kernel(const float* __restrict__ x) {
    int warp = (blockIdx.x * blockDim.x + threadIdx.x) >> 5;
    int lane = threadIdx.x & 31;
    if (warp >= NROWS) return;
    const float4* xr = reinterpret_cast<const float4*>(x + (size_t)warp * CDIM);
    float4 v0 = xr[lane * 2 + 0];
    float4 v1 = xr[lane * 2 + 1];
    float s = v0.x * v0.x + v0.y * v0.y + v0.z * v0.z + v0.w * v0.w
            + v1.x * v1.x + v1.y * v1.y + v1.z * v1.z + v1.w * v1.w;
#pragma unroll
    for (int off = 16; off > 0; off >>= 1)
        s += __shfl_xor_sync(0xFFFFFFFFu, s, off);
    if (lane == 0) {
        g_sq[warp]  = s;
        g_hp2[warp] = 0.0f;
        g_hn2[warp] = __int_as_float(FLTMAX_BITS);
    }
}

// ---------------------------------------------------------------------------
// Kernel 2: symmetric fused Gram + mining. One 128x128 tile (it<=jt) per
// block. FFMA2 (fma.rn.f32x2) main loop, accumulators paired along m.
// Row mining for rows i (tile rows), column mining for rows j (tile cols).
// Same-label within a tile <=> local row == local col (labels are i%128 and
// tiles are 128-aligned), so positives live only on the tile diagonal.
// ---------------------------------------------------------------------------
__global__ void __launch_bounds__(NTHREADS, 2)
pair_kernel(const float* __restrict__ x) {
    __shared__ __align__(16) float As[BK][BM + 4];
    __shared__ __align__(16) float Bs[BK][BN + 4];

    const int tid = threadIdx.x;
    const int tx = tid & 15;        // 0..15, column group
    const int ty = tid >> 4;        // 0..15, row group

    // Triangular tile decode: C(r) = r*(129-r)/2 tiles precede row r.
    int t = blockIdx.x;
    int it = (int)floorf((129.0f - sqrtf(129.0f * 129.0f - 8.0f * (float)t)) * 0.5f);
    while (it > 0 && (it * (129 - it)) / 2 > t) it--;
    while (((it + 1) * (129 - (it + 1))) / 2 <= t) it++;
    const int jt = it + (t - (it * (129 - it)) / 2);
    const int iBase = it * BM;
    const int jBase = jt * BN;
    const bool dtile = (it == jt);

    // Accumulators: acc2[m2][n] packs rows (2*m2, 2*m2+1) of the thread tile.
    unsigned long long acc2[TM / 2][TN];
#pragma unroll
    for (int m2 = 0; m2 < TM / 2; m2++)
#pragma unroll
        for (int n = 0; n < TN; n++) acc2[m2][n] = 0ull;

    const int lr = tid >> 2;         // 0..63
    const int lk = (tid & 3) * 4;    // 0,4,8,12

    for (int k0 = 0; k0 < CDIM; k0 += BK) {
        float4 a0 = *reinterpret_cast<const float4*>(&x[(size_t)(iBase + lr)      * CDIM + k0 + lk]);
        float4 a1 = *reinterpret_cast<const float4*>(&x[(size_t)(iBase + lr + 64) * CDIM + k0 + lk]);
        float4 b0 = *reinterpret_cast<const float4*>(&x[(size_t)(jBase + lr)      * CDIM + k0 + lk]);
        float4 b1 = *reinterpret_cast<const float4*>(&x[(size_t)(jBase + lr + 64) * CDIM + k0 + lk]);
        As[lk + 0][lr] = a0.x; As[lk + 1][lr] = a0.y; As[lk + 2][lr] = a0.z; As[lk + 3][lr] = a0.w;
        As[lk + 0][lr + 64] = a1.x; As[lk + 1][lr + 64] = a1.y; As[lk + 2][lr + 64] = a1.z; As[lk + 3][lr + 64] = a1.w;
        Bs[lk + 0][lr] = b0.x; Bs[lk + 1][lr] = b0.y; Bs[lk + 2][lr] = b0.z; Bs[lk + 3][lr] = b0.w;
        Bs[lk + 0][lr + 64] = b1.x; Bs[lk + 1][lr + 64] = b1.y; Bs[lk + 2][lr + 64] = b1.z; Bs[lk + 3][lr + 64] = b1.w;
        __syncthreads();

#pragma unroll
        for (int k = 0; k < BK; k++) {
            // A pairs: contiguous rows in As -> direct 64-bit packed loads.
            ulonglong2 av0 = *reinterpret_cast<const ulonglong2*>(&As[k][ty * TM]);
            ulonglong2 av1 = *reinterpret_cast<const ulonglong2*>(&As[k][ty * TM + 4]);
            unsigned long long a2[4] = {av0.x, av0.y, av1.x, av1.y};
            // B: load 8 floats, duplicate each into a packed pair.
            float4 b0r = *reinterpret_cast<const float4*>(&Bs[k][tx * TN]);
            float4 b1r = *reinterpret_cast<const float4*>(&Bs[k][tx * TN + 4]);
            unsigned long long b2[8];
            PACKDUP_F32X2(b2[0], b0r.x); PACKDUP_F32X2(b2[1], b0r.y);
            PACKDUP_F32X2(b2[2], b0r.z); PACKDUP_F32X2(b2[3], b0r.w);
            PACKDUP_F32X2(b2[4], b1r.x); PACKDUP_F32X2(b2[5], b1r.y);
            PACKDUP_F32X2(b2[6], b1r.z); PACKDUP_F32X2(b2[7], b1r.w);
#pragma unroll
            for (int m2 = 0; m2 < TM / 2; m2++)
#pragma unroll
                for (int n = 0; n < TN; n++)
                    FMA_F32X2(acc2[m2][n], a2[m2], b2[n], acc2[m2][n]);
        }
        __syncthreads();
    }

    // ---------------- Epilogue: mine squared distances ----------------
    const bool dthr = (ty == tx);
    const float FMAXV = __int_as_float(FLTMAX_BITS);

    float sqj[TN];
#pragma unroll
    for (int n = 0; n < TN; n++) sqj[n] = g_sq[jBase + tx * TN + n];

    float cp_hp[TN], cp_hn[TN];
#pragma unroll
    for (int n = 0; n < TN; n++) { cp_hp[n] = 0.0f; cp_hn[n] = FMAXV; }

#pragma unroll
    for (int m2 = 0; m2 < TM / 2; m2++) {
#pragma unroll
        for (int sub = 0; sub < 2; sub++) {
            const int m = 2 * m2 + sub;
            const float sqi = g_sq[iBase + ty * TM + m];
            float rp_hp = 0.0f, rp_hn = FMAXV;
#pragma unroll
            for (int n = 0; n < TN; n++) {
                float lo, hi;
                UNPACK_F32X2(lo, hi, acc2[m2][n]);
                float v = sub ? hi : lo;
                float d2 = fmaxf(fmaf(-2.0f, v, sqi + sqj[n]), 0.0f);
                if (m == n) {  // compile-time: possible positive slot
                    if (dthr) {
                        if (!dtile) {  // on diag tiles this is i==j: excluded
                            rp_hp = fmaxf(rp_hp, d2);
                            cp_hp[n] = fmaxf(cp_hp[n], d2);
                        }
                    } else {
                        rp_hn = fminf(rp_hn, d2);
                        cp_hn[n] = fminf(cp_hn[n], d2);
                    }
                } else {
                    rp_hn = fminf(rp_hn, d2);
                    cp_hn[n] = fminf(cp_hn[n], d2);
                }
            }
            // Row reduce across the 16 tx lanes (stays in warp half).
#pragma unroll
            for (int off = 8; off > 0; off >>= 1) {
                rp_hp = fmaxf(rp_hp, __shfl_xor_sync(0xFFFFFFFFu, rp_hp, off));
                rp_hn = fminf(rp_hn, __shfl_xor_sync(0xFFFFFFFFu, rp_hn, off));
            }
            if (tx == 0) {
                const int row = iBase + ty * TM + m;
                if (rp_hp > 0.0f)
                    atomicMax(reinterpret_cast<int*>(&g_hp2[row]), __float_as_int(rp_hp));
                atomicMin(reinterpret_cast<int*>(&g_hn2[row]), __float_as_int(rp_hn));
            }
        }
    }

    // Column reduce via smem staging (reuse As/Bs; all tile reads are done).
    if (!dtile) {
#pragma unroll
        for (int n = 0; n < TN; n++) {
            As[ty][tx * TN + n] = cp_hn[n];
            Bs[ty][tx * TN + n] = cp_hp[n];
        }
        __syncthreads();
        if (tid < BN) {
            float chn = FMAXV, chp = 0.0f;
#pragma unroll
            for (int r = 0; r < 16; r++) {
                chn = fminf(chn, As[r][tid]);
                chp = fmaxf(chp, Bs[r][tid]);
            }
            const int col = jBase + tid;
            if (chp > 0.0f)
                atomicMax(reinterpret_cast<int*>(&g_hp2[col]), __float_as_int(chp));
            atomicMin(reinterpret_cast<int*>(&g_hn2[col]), __float_as_int(chn));
        }
    }
}

// ---------------------------------------------------------------------------
// Kernel 3: final scalar = dr + t_loss + mse. Single block, deterministic.
// ---------------------------------------------------------------------------
__global__ void final_kernel(const float* __restrict__ gt,
                             const float* __restrict__ s0,
                             const float* __restrict__ s1,
                             const float* __restrict__ s2,
                             const float* __restrict__ e0,
                             const float* __restrict__ e1,
                             const float* __restrict__ l0,
                             const float* __restrict__ l1,
                             float* __restrict__ out) {
    __shared__ float red[NTHREADS];
    const int tid = threadIdx.x;

    float tsum = 0.0f;
    for (int i = tid; i < NROWS; i += NTHREADS) {
        float hp = sqrtf(g_hp2[i]);
        float hn = sqrtf(g_hn2[i]);
        tsum += fmaxf(hp - hn + MARGIN, 0.0f);
    }

    float msum = 0.0f;
    for (int i = tid; i < BQ; i += NTHREADS) {
        float g = gt[i];
        float a = s0[i] - g, b = s1[i] - g, c = s2[i] - g;
        msum += a * a + b * b + c * c;
    }

    float dsum = 0.0f;
    for (int i = tid; i < DDIM; i += NTHREADS) {
        dsum += fabsf(e0[i] - l0[i]) + fabsf(e1[i] - l1[i]);
    }

    float vals[3] = {tsum, msum, dsum};
    float res[3];
#pragma unroll
    for (int v = 0; v < 3; v++) {
        red[tid] = vals[v];
        __syncthreads();
        for (int s = NTHREADS / 2; s > 0; s >>= 1) {
            if (tid < s) red[tid] += red[tid + s];
            __syncthreads();
        }
        res[v] = red[0];
        __syncthreads();
    }

    if (tid == 0) {
        float t_loss = res[0] / (float)NROWS;
        float mse    = res[1] / (float)(BQ * 3);
        float dr     = res[2] / (float)DDIM;
        out[0] = dr + t_loss + mse;
    }
}

// ---------------------------------------------------------------------------
extern "C" void kernel_launch(void* const* d_in, const int* in_sizes, int n_in,
                              void* d_out, int out_size) {
    const float* feat = (const float*)d_in[0];
    const float* gt   = (const float*)d_in[1];
    const float* s0   = (const float*)d_in[2];
    const float* s1   = (const float*)d_in[3];
    const float* s2   = (const float*)d_in[4];
    const float* e0   = (const float*)d_in[5];
    const float* e1   = (const float*)d_in[6];
    const float* l0   = (const float*)d_in[7];
    const float* l1   = (const float*)d_in[8];
    float* out = (float*)d_out;

    init_kernel<<<NROWS * 32 / NTHREADS, NTHREADS>>>(feat);
    pair_kernel<<<NPAIRTILES, NTHREADS>>>(feat);
    final_kernel<<<1, NTHREADS>>>(gt, s0, s1, s2, e0, e1, l0, l1, out);
}

// round 4
// speedup vs baseline: 4.4606x; 2.2866x over previous
#include <cuda_runtime.h>
#include <cuda_bf16.h>
#include <math.h>
#include <stdint.h>

// ---------------- problem constants ----------------
#define NROWS 8192      // b*n
#define CDIM  256
#define NTILES 64
#define NPAIRTILES 2080 // NTILES*(NTILES+1)/2
#define BQ    64
#define DDIM  65536
#define MARGIN 0.3f
#define FLTMAX_BITS 0x7F7FFFFF

#define NTHREADS 256
#define TILE_BYTES 16384           // one 128x(64 bf16) operand chunk, swizzled
#define STAGE_BYTES (4 * TILE_BYTES)  // Ah, Al, Bh, Bl
#define SMEM_DYN (2 * STAGE_BYTES + 1024)
#define NDRBLK 64

// ---------------- device globals (no allocs allowed) ----------------
__device__ __align__(128) __nv_bfloat16 g_P[(size_t)NROWS * 512]; // [hi(256)|lo(256)]
__device__ float g_sq[NROWS];
__device__ float g_hp2[NROWS];
__device__ float g_hn2[NROWS];
__device__ float g_dpart[NDRBLK];

// ---------------- PTX helpers (all baseline sm_80-class, no 'a' features) ---
__device__ __forceinline__ uint32_t smem_u32(const void* p) {
    uint32_t a;
    asm("{ .reg .u64 t; cvta.to.shared.u64 t, %1; cvt.u32.u64 %0, t; }" : "=r"(a) : "l"(p));
    return a;
}

#define CP_ASYNC16(dst, src) \
    asm volatile("cp.async.cg.shared.global [%0], [%1], 16;" :: "r"(dst), "l"(src) : "memory")
#define CP_COMMIT() asm volatile("cp.async.commit_group;" ::: "memory")

#define LDSM4(r, addr) \
    asm volatile("ldmatrix.sync.aligned.m8n8.x4.shared.b16 {%0,%1,%2,%3}, [%4];" \
        : "=r"((r)[0]), "=r"((r)[1]), "=r"((r)[2]), "=r"((r)[3]) : "r"(addr))

#define MMA16816(d, a, b0, b1) \
    asm volatile("mma.sync.aligned.m16n8k16.row.col.f32.bf16.bf16.f32 " \
        "{%0,%1,%2,%3}, {%4,%5,%6,%7}, {%8,%9}, {%0,%1,%2,%3};" \
        : "+f"((d)[0]), "+f"((d)[1]), "+f"((d)[2]), "+f"((d)[3]) \
        : "r"((a)[0]), "r"((a)[1]), "r"((a)[2]), "r"((a)[3]), "r"(b0), "r"(b1))

// ---------------------------------------------------------------------------
// Kernel 0: split feat into bf16 hi/lo packed per row: [hi(256)|lo(256)].
// ---------------------------------------------------------------------------
__device__ __forceinline__ unsigned f2bf_bits(float a) {
    unsigned b = __float_as_uint(a);
    return (b + 0x7FFFu + ((b >> 16) & 1u)) >> 16;   // rn-even (finite inputs)
}

__global__ void prep_kernel(const float* __restrict__ x) {
    int q = blockIdx.x * blockDim.x + threadIdx.x;   // one per 4 floats
    int r = q >> 6;
    int c4 = (q & 63) << 2;
    const float4 v = *reinterpret_cast<const float4*>(x + (size_t)r * CDIM + c4);
    float a[4] = {v.x, v.y, v.z, v.w};
    unsigned hb[4], lb[4];
#pragma unroll
    for (int i = 0; i < 4; i++) {
        hb[i] = f2bf_bits(a[i]);
        float ahf = __uint_as_float(hb[i] << 16);
        lb[i] = f2bf_bits(a[i] - ahf);
    }
    uint2 ph = make_uint2(hb[0] | (hb[1] << 16), hb[2] | (hb[3] << 16));
    uint2 pl = make_uint2(lb[0] | (lb[1] << 16), lb[2] | (lb[3] << 16));
    size_t base = (size_t)r * 512 + c4;
    *reinterpret_cast<uint2*>(&g_P[base])       = ph;
    *reinterpret_cast<uint2*>(&g_P[base + 256]) = pl;
}

// ---------------------------------------------------------------------------
// Kernel 1: per-row squared norms (fp32 exact) + reset hp2/hn2.
// ---------------------------------------------------------------------------
__global__ void init_kernel(const float* __restrict__ x) {
    int warp = (blockIdx.x * blockDim.x + threadIdx.x) >> 5;
    int lane = threadIdx.x & 31;
    if (warp >= NROWS) return;
    const float4* xr = reinterpret_cast<const float4*>(x + (size_t)warp * CDIM);
    float4 v0 = xr[lane * 2 + 0];
    float4 v1 = xr[lane * 2 + 1];
    float s = v0.x * v0.x + v0.y * v0.y + v0.z * v0.z + v0.w * v0.w
            + v1.x * v1.x + v1.y * v1.y + v1.z * v1.z + v1.w * v1.w;
#pragma unroll
    for (int off = 16; off > 0; off >>= 1)
        s += __shfl_xor_sync(0xFFFFFFFFu, s, off);
    if (lane == 0) {
        g_sq[warp]  = s;
        g_hp2[warp] = 0.0f;
        g_hn2[warp] = __int_as_float(FLTMAX_BITS);
    }
}

// ---------------------------------------------------------------------------
// Load one 64-col chunk kc (of 4) into a stage: Ah, Al (rows iBase..), Bh, Bl
// (rows jBase..). 16 cp.async x 16B per thread, SW128 swizzle.
// ---------------------------------------------------------------------------
__device__ __forceinline__ void load_chunk(uint32_t stage, int iBase, int jBase,
                                           int kc, int tid) {
    const int cu = tid & 7;          // 16B column unit
    const int r0 = tid >> 3;         // 0..31
    const uint32_t colsw = ((uint32_t)(cu * 16)) ^ (((uint32_t)(r0 & 7)) << 4);
    const int ecol = kc * 64 + cu * 8;  // element col within hi block
#pragma unroll
    for (int i = 0; i < 4; i++) {
        const int row = r0 + 32 * i;
        const uint32_t dst = stage + (uint32_t)row * 128u + colsw;
        const __nv_bfloat16* srcA = &g_P[(size_t)(iBase + row) * 512 + ecol];
        const __nv_bfloat16* srcB = &g_P[(size_t)(jBase + row) * 512 + ecol];
        CP_ASYNC16(dst,                  srcA);        // Ah
        CP_ASYNC16(dst + TILE_BYTES,     srcA + 256);  // Al
        CP_ASYNC16(dst + 2 * TILE_BYTES, srcB);        // Bh
        CP_ASYNC16(dst + 3 * TILE_BYTES, srcB + 256);  // Bl
    }
    CP_COMMIT();
}

// ---------------------------------------------------------------------------
// Kernel 2: warp-MMA fused Gram + mining, one 128x128 tile (it<=jt) per CTA.
// 3 passes per chunk: Ah*Bh + Al*Bh + Ah*Bl (bf16 split, fp32 accum).
// ---------------------------------------------------------------------------
__global__ void __launch_bounds__(NTHREADS, 1) pair_mma_kernel() {
    extern __shared__ __align__(16) char dsm[];
    __shared__ float s_sqi[128], s_sqj[128], s_diag[128];
    __shared__ int s_rowmin[128], s_colmin[128];

    const int tid = threadIdx.x;
    const int wid = tid >> 5;
    const int lane = tid & 31;
    const int wm = wid & 3;          // 4 warps along m
    const int wn = wid >> 2;         // 2 warps along n
    const int lrow = lane & 15;
    const int lcolb = (lane >> 4) * 16;
    const uint32_t lxor = ((uint32_t)(lrow & 7)) << 4;

    // triangular tile decode
    int t = blockIdx.x;
    int it = (int)floorf((129.0f - sqrtf(129.0f * 129.0f - 8.0f * (float)t)) * 0.5f);
    while (it > 0 && (it * (129 - it)) / 2 > t) it--;
    while (((it + 1) * (129 - (it + 1))) / 2 <= t) it++;
    const int jt = it + (t - (it * (129 - it)) / 2);
    const int iBase = it * 128;
    const int jBase = jt * 128;
    const bool dtile = (it == jt);

    const uint32_t sb = smem_u32(dsm);
    const uint32_t stage0 = (sb + 1023u) & ~1023u;
    const uint32_t stage1 = stage0 + STAGE_BYTES;

    if (tid < 128) {
        s_sqi[tid] = g_sq[iBase + tid];
        s_sqj[tid] = g_sq[jBase + tid];
        s_rowmin[tid] = FLTMAX_BITS;
        s_colmin[tid] = FLTMAX_BITS;
    }

    float acc[2][8][4];
#pragma unroll
    for (int mf = 0; mf < 2; mf++)
#pragma unroll
        for (int nf = 0; nf < 8; nf++)
#pragma unroll
            for (int r = 0; r < 4; r++) acc[mf][nf][r] = 0.0f;

    load_chunk(stage0, iBase, jBase, 0, tid);
    load_chunk(stage1, iBase, jBase, 1, tid);

#pragma unroll 1
    for (int kc = 0; kc < 4; kc++) {
        const uint32_t stage = (kc & 1) ? stage1 : stage0;
        if (kc < 3) asm volatile("cp.async.wait_group 1;" ::: "memory");
        else        asm volatile("cp.async.wait_group 0;" ::: "memory");
        __syncthreads();

#pragma unroll
        for (int p = 0; p < 3; p++) {
            const uint32_t aB = stage + (p == 1 ? (uint32_t)TILE_BYTES : 0u)
                              + (uint32_t)(wm * 32 + lrow) * 128u;
            const uint32_t bB = stage + (p == 2 ? 3u * TILE_BYTES : 2u * TILE_BYTES)
                              + (uint32_t)(wn * 64 + lrow) * 128u;
#pragma unroll
            for (int ks = 0; ks < 4; ks++) {
                const uint32_t csw = ((uint32_t)(ks * 32 + lcolb)) ^ lxor;
                uint32_t a0[4], a1[4];
                LDSM4(a0, aB + csw);
                LDSM4(a1, aB + 16 * 128 + csw);
#pragma unroll
                for (int ng = 0; ng < 4; ng++) {
                    uint32_t br[4];
                    LDSM4(br, bB + (uint32_t)(ng * 16 * 128) + csw);
                    MMA16816(acc[0][2 * ng],     a0, br[0], br[2]);
                    MMA16816(acc[0][2 * ng + 1], a0, br[1], br[3]);
                    MMA16816(acc[1][2 * ng],     a1, br[0], br[2]);
                    MMA16816(acc[1][2 * ng + 1], a1, br[1], br[3]);
                }
            }
        }
        __syncthreads();
        if (kc + 2 < 4)
            load_chunk(stage, iBase, jBase, kc + 2, tid);
    }

    // ---------------- mining epilogue ----------------
    const int groupId = lane >> 2;
    const int tid4 = lane & 3;
    const float INFV = __int_as_float(0x7F800000);

    float rmin[2][2];    // [mf][rowhalf]
    float cmin[8][2];    // [nf][colparity]
#pragma unroll
    for (int mf = 0; mf < 2; mf++) { rmin[mf][0] = INFV; rmin[mf][1] = INFV; }
#pragma unroll
    for (int nf = 0; nf < 8; nf++) { cmin[nf][0] = INFV; cmin[nf][1] = INFV; }

#pragma unroll
    for (int mf = 0; mf < 2; mf++) {
#pragma unroll
        for (int nf = 0; nf < 8; nf++) {
#pragma unroll
            for (int r = 0; r < 4; r++) {
                const int row_l = wm * 32 + mf * 16 + groupId + (r >> 1) * 8;
                const int col_l = wn * 64 + nf * 8 + tid4 * 2 + (r & 1);
                const float dot = acc[mf][nf][r];
                float d2 = fmaxf(fmaf(dot, -2.0f, s_sqi[row_l]) + s_sqj[col_l], 0.0f);
                if (row_l == col_l) {
                    s_diag[row_l] = d2;
                } else {
                    rmin[mf][r >> 1] = fminf(rmin[mf][r >> 1], d2);
                    cmin[nf][r & 1]  = fminf(cmin[nf][r & 1], d2);
                }
            }
        }
    }

    // row reduce over tid4 (lanes sharing the same rows)
#pragma unroll
    for (int mf = 0; mf < 2; mf++) {
#pragma unroll
        for (int h = 0; h < 2; h++) {
            float v = rmin[mf][h];
            v = fminf(v, __shfl_xor_sync(0xFFFFFFFFu, v, 1));
            v = fminf(v, __shfl_xor_sync(0xFFFFFFFFu, v, 2));
            if (tid4 == 0)
                atomicMin(&s_rowmin[wm * 32 + mf * 16 + groupId + 8 * h], __float_as_int(v));
        }
    }
    // col reduce over groupId (lanes sharing the same cols)
#pragma unroll
    for (int nf = 0; nf < 8; nf++) {
#pragma unroll
        for (int par = 0; par < 2; par++) {
            float v = cmin[nf][par];
            v = fminf(v, __shfl_xor_sync(0xFFFFFFFFu, v, 4));
            v = fminf(v, __shfl_xor_sync(0xFFFFFFFFu, v, 8));
            v = fminf(v, __shfl_xor_sync(0xFFFFFFFFu, v, 16));
            if (groupId == 0)
                atomicMin(&s_colmin[wn * 64 + nf * 8 + tid4 * 2 + par], __float_as_int(v));
        }
    }
    __syncthreads();

    if (tid < 128) {
        const int row = iBase + tid;
        atomicMin(reinterpret_cast<int*>(&g_hn2[row]), s_rowmin[tid]);
        if (!dtile) {
            const int col = jBase + tid;
            atomicMin(reinterpret_cast<int*>(&g_hn2[col]), s_colmin[tid]);
            const int db = __float_as_int(s_diag[tid]);
            atomicMax(reinterpret_cast<int*>(&g_hp2[row]), db);
            atomicMax(reinterpret_cast<int*>(&g_hp2[col]), db);
        }
    }
}

// ---------------------------------------------------------------------------
// Kernel 3: L1 (dr) partial sums, 64 blocks, deterministic per-block tree.
// ---------------------------------------------------------------------------
__global__ void dr_kernel(const float* __restrict__ e0,
                          const float* __restrict__ e1,
                          const float* __restrict__ l0,
                          const float* __restrict__ l1) {
    __shared__ float red[256];
    const int tid = threadIdx.x;
    const int base = blockIdx.x * (DDIM / NDRBLK);
    float s = 0.0f;
#pragma unroll
    for (int k = 0; k < DDIM / NDRBLK / 256; k++) {
        int i = base + k * 256 + tid;
        s += fabsf(e0[i] - l0[i]) + fabsf(e1[i] - l1[i]);
    }
    red[tid] = s;
    __syncthreads();
    for (int st = 128; st > 0; st >>= 1) {
        if (tid < st) red[tid] += red[tid + st];
        __syncthreads();
    }
    if (tid == 0) g_dpart[blockIdx.x] = red[0];
}

// ---------------------------------------------------------------------------
// Kernel 4: final scalar = dr + t_loss + mse. Single block, deterministic.
// ---------------------------------------------------------------------------
__global__ void final_kernel(const float* __restrict__ gt,
                             const float* __restrict__ s0,
                             const float* __restrict__ s1,
                             const float* __restrict__ s2,
                             float* __restrict__ out) {
    __shared__ float red[256];
    const int tid = threadIdx.x;

    float tsum = 0.0f;
    for (int i = tid; i < NROWS; i += 256) {
        float hp = sqrtf(fmaxf(g_hp2[i], 0.0f));
        float hn = sqrtf(fmaxf(g_hn2[i], 0.0f));
        tsum += fmaxf(hp - hn + MARGIN, 0.0f);
    }

    float msum = 0.0f;
    if (tid < BQ) {
        float g = gt[tid];
        float a = s0[tid] - g, b = s1[tid] - g, c = s2[tid] - g;
        msum = a * a + b * b + c * c;
    }

    float dsum = (tid < NDRBLK) ? g_dpart[tid] : 0.0f;

    float vals[3] = {tsum, msum, dsum};
    float res[3];
#pragma unroll
    for (int v = 0; v < 3; v++) {
        red[tid] = vals[v];
        __syncthreads();
        for (int st = 128; st > 0; st >>= 1) {
            if (tid < st) red[tid] += red[tid + st];
            __syncthreads();
        }
        res[v] = red[0];
        __syncthreads();
    }

    if (tid == 0) {
        float t_loss = res[0] / (float)NROWS;
        float mse    = res[1] / (float)(BQ * 3);
        float dr     = res[2] / (float)DDIM;
        out[0] = dr + t_loss + mse;
    }
}

// ---------------------------------------------------------------------------
extern "C" void kernel_launch(void* const* d_in, const int* in_sizes, int n_in,
                              void* d_out, int out_size) {
    const float* feat = (const float*)d_in[0];
    const float* gt   = (const float*)d_in[1];
    const float* s0   = (const float*)d_in[2];
    const float* s1   = (const float*)d_in[3];
    const float* s2   = (const float*)d_in[4];
    const float* e0   = (const float*)d_in[5];
    const float* e1   = (const float*)d_in[6];
    const float* l0   = (const float*)d_in[7];
    const float* l1   = (const float*)d_in[8];
    float* out = (float*)d_out;

    cudaFuncSetAttribute(pair_mma_kernel,
                         cudaFuncAttributeMaxDynamicSharedMemorySize, SMEM_DYN);

    init_kernel<<<NROWS * 32 / 256, 256>>>(feat);
    prep_kernel<<<NROWS * CDIM / 4 / 256, 256>>>(feat);
    pair_mma_kernel<<<NPAIRTILES, NTHREADS, SMEM_DYN>>>();
    dr_kernel<<<NDRBLK, 256>>>(e0, e1, l0, l1);
    final_kernel<<<1, 256>>>(gt, s0, s1, s2, out);
}

// round 5
// speedup vs baseline: 7.0661x; 1.5841x over previous
#include <cuda_runtime.h>
#include <cuda_bf16.h>
#include <math.h>
#include <stdint.h>

// ---------------- problem constants ----------------
#define NROWS 8192      // b*n
#define CDIM  256
#define NTILES 64
#define NPAIRTILES 2080 // NTILES*(NTILES+1)/2
#define BQ    64
#define DDIM  65536
#define MARGIN 0.3f
#define FLTMAX_BITS 0x7F7FFFFF

#define NTHREADS 128               // 4 warps, each 64x64
#define TILE_BYTES 16384           // 128 rows x 128B (64 bf16 cols)
#define STAGE_BYTES (3 * TILE_BYTES)  // Ah, Al, Bh
#define SMEM_DYN (2 * STAGE_BYTES + 1024)
#define NDRBLK 64
#define NPREPBLK 1024              // 8 rows per block (8 warps x 256 thr)

// ---------------- device globals (no allocs allowed) ----------------
__device__ __align__(128) __nv_bfloat16 g_P[(size_t)NROWS * 512]; // [hi(256)|lo(256)]
__device__ float g_sq[NROWS];
__device__ float g_hp2[NROWS];
__device__ float g_hn2[NROWS];
__device__ float g_dpart[NDRBLK];

// ---------------- PTX helpers (baseline sm_80-class only) ----------------
__device__ __forceinline__ uint32_t smem_u32(const void* p) {
    uint32_t a;
    asm("{ .reg .u64 t; cvta.to.shared.u64 t, %1; cvt.u32.u64 %0, t; }" : "=r"(a) : "l"(p));
    return a;
}

#define CP_ASYNC16(dst, src) \
    asm volatile("cp.async.cg.shared.global [%0], [%1], 16;" :: "r"(dst), "l"(src) : "memory")
#define CP_COMMIT() asm volatile("cp.async.commit_group;" ::: "memory")

#define LDSM4(r, addr) \
    asm volatile("ldmatrix.sync.aligned.m8n8.x4.shared.b16 {%0,%1,%2,%3}, [%4];" \
        : "=r"((r)[0]), "=r"((r)[1]), "=r"((r)[2]), "=r"((r)[3]) : "r"(addr))

#define MMA16816(d, a, b0, b1) \
    asm volatile("mma.sync.aligned.m16n8k16.row.col.f32.bf16.bf16.f32 " \
        "{%0,%1,%2,%3}, {%4,%5,%6,%7}, {%8,%9}, {%0,%1,%2,%3};" \
        : "+f"((d)[0]), "+f"((d)[1]), "+f"((d)[2]), "+f"((d)[3]) \
        : "r"((a)[0]), "r"((a)[1]), "r"((a)[2]), "r"((a)[3]), "r"(b0), "r"(b1))

__device__ __forceinline__ unsigned f2bf_bits(float a) {
    unsigned b = __float_as_uint(a);
    return (b + 0x7FFFu + ((b >> 16) & 1u)) >> 16;   // rn-even (finite inputs)
}

// ---------------------------------------------------------------------------
// Kernel 0 (fused): blocks [0,1024): prep (bf16 hi/lo split) + row norms +
// hp/hn reset, one warp per row. Blocks [1024,1088): dr (L1) partial sums.
// ---------------------------------------------------------------------------
__global__ void prep_kernel(const float* __restrict__ x,
                            const float* __restrict__ e0,
                            const float* __restrict__ e1,
                            const float* __restrict__ l0,
                            const float* __restrict__ l1) {
    const int tid = threadIdx.x;
    if (blockIdx.x < NPREPBLK) {
        const int wid = tid >> 5, lane = tid & 31;
        const int row = blockIdx.x * 8 + wid;
        const float4* xr = reinterpret_cast<const float4*>(x + (size_t)row * CDIM);
        float4 v0 = xr[lane * 2 + 0];
        float4 v1 = xr[lane * 2 + 1];
        float a[8] = {v0.x, v0.y, v0.z, v0.w, v1.x, v1.y, v1.z, v1.w};
        float s = 0.0f;
        unsigned hb[8], lb[8];
#pragma unroll
        for (int i = 0; i < 8; i++) {
            s = fmaf(a[i], a[i], s);
            hb[i] = f2bf_bits(a[i]);
            float ahf = __uint_as_float(hb[i] << 16);
            lb[i] = f2bf_bits(a[i] - ahf);
        }
        uint4 ph = make_uint4(hb[0] | (hb[1] << 16), hb[2] | (hb[3] << 16),
                              hb[4] | (hb[5] << 16), hb[6] | (hb[7] << 16));
        uint4 pl = make_uint4(lb[0] | (lb[1] << 16), lb[2] | (lb[3] << 16),
                              lb[4] | (lb[5] << 16), lb[6] | (lb[7] << 16));
        size_t base = (size_t)row * 512 + lane * 8;
        *reinterpret_cast<uint4*>(&g_P[base])       = ph;
        *reinterpret_cast<uint4*>(&g_P[base + 256]) = pl;
#pragma unroll
        for (int off = 16; off > 0; off >>= 1)
            s += __shfl_xor_sync(0xFFFFFFFFu, s, off);
        if (lane == 0) {
            g_sq[row]  = s;
            g_hp2[row] = 0.0f;
            g_hn2[row] = __int_as_float(FLTMAX_BITS);
        }
    } else {
        __shared__ float red[256];
        const int b = blockIdx.x - NPREPBLK;
        const int base = b * (DDIM / NDRBLK);
        float s = 0.0f;
#pragma unroll
        for (int k = 0; k < DDIM / NDRBLK / 256; k++) {
            int i = base + k * 256 + tid;
            s += fabsf(e0[i] - l0[i]) + fabsf(e1[i] - l1[i]);
        }
        red[tid] = s;
        __syncthreads();
        for (int st = 128; st > 0; st >>= 1) {
            if (tid < st) red[tid] += red[tid + st];
            __syncthreads();
        }
        if (tid == 0) g_dpart[b] = red[0];
    }
}

// ---------------------------------------------------------------------------
// Load one 64-col chunk kc into a stage: Ah, Al (rows iBase..), Bh (jBase..).
// 128 threads x 24 cp.async x 16B, SW128 swizzle.
// ---------------------------------------------------------------------------
__device__ __forceinline__ void load_chunk(uint32_t stage, int iBase, int jBase,
                                           int kc, int tid) {
    const int cu = tid & 7;          // 16B column unit
    const int r0 = tid >> 3;         // 0..15
    const uint32_t colsw = ((uint32_t)(cu * 16)) ^ (((uint32_t)(r0 & 7)) << 4);
    const int ecol = kc * 64 + cu * 8;
#pragma unroll
    for (int i = 0; i < 8; i++) {
        const int row = r0 + 16 * i;
        const uint32_t dst = stage + (uint32_t)row * 128u + colsw;
        const __nv_bfloat16* srcA = &g_P[(size_t)(iBase + row) * 512 + ecol];
        const __nv_bfloat16* srcB = &g_P[(size_t)(jBase + row) * 512 + ecol];
        CP_ASYNC16(dst,                  srcA);        // Ah
        CP_ASYNC16(dst + TILE_BYTES,     srcA + 256);  // Al
        CP_ASYNC16(dst + 2 * TILE_BYTES, srcB);        // Bh
    }
    CP_COMMIT();
}

// ---------------------------------------------------------------------------
// Kernel 1: warp-MMA fused Gram + mining, one 128x128 tile (it<=jt) per CTA.
// 2-term A-split: (ah + al) * bh, fp32 accum. 4 warps, 64x64 each; B frags
// reused across both A passes.
// ---------------------------------------------------------------------------
__global__ void __launch_bounds__(NTHREADS) pair_mma_kernel() {
    extern __shared__ __align__(16) char dsm[];
    __shared__ float s_sqi[128], s_sqj[128], s_diag[128];
    __shared__ int s_rowmin[128], s_colmin[128];

    const int tid = threadIdx.x;
    const int wid = tid >> 5;
    const int lane = tid & 31;
    const int wm = wid & 1;          // 2 warps along m
    const int wn = wid >> 1;         // 2 warps along n
    const int lrow = lane & 15;
    const int lcolb = (lane >> 4) * 16;
    const uint32_t lxor = ((uint32_t)(lrow & 7)) << 4;

    // triangular tile decode
    int t = blockIdx.x;
    int it = (int)floorf((129.0f - sqrtf(129.0f * 129.0f - 8.0f * (float)t)) * 0.5f);
    while (it > 0 && (it * (129 - it)) / 2 > t) it--;
    while (((it + 1) * (129 - (it + 1))) / 2 <= t) it++;
    const int jt = it + (t - (it * (129 - it)) / 2);
    const int iBase = it * 128;
    const int jBase = jt * 128;
    const bool dtile = (it == jt);

    const uint32_t sb = smem_u32(dsm);
    const uint32_t stage0 = (sb + 1023u) & ~1023u;
    const uint32_t stage1 = stage0 + STAGE_BYTES;

    if (tid < 128) {
        s_sqi[tid] = g_sq[iBase + tid];
        s_sqj[tid] = g_sq[jBase + tid];
        s_rowmin[tid] = FLTMAX_BITS;
        s_colmin[tid] = FLTMAX_BITS;
    }

    float acc[4][8][4];
#pragma unroll
    for (int mf = 0; mf < 4; mf++)
#pragma unroll
        for (int nf = 0; nf < 8; nf++)
#pragma unroll
            for (int r = 0; r < 4; r++) acc[mf][nf][r] = 0.0f;

    load_chunk(stage0, iBase, jBase, 0, tid);
    load_chunk(stage1, iBase, jBase, 1, tid);

#pragma unroll 1
    for (int kc = 0; kc < 4; kc++) {
        const uint32_t stage = (kc & 1) ? stage1 : stage0;
        if (kc < 3) asm volatile("cp.async.wait_group 1;" ::: "memory");
        else        asm volatile("cp.async.wait_group 0;" ::: "memory");
        __syncthreads();

        const uint32_t aHB = stage + (uint32_t)(wm * 64 + lrow) * 128u;
        const uint32_t aLB = aHB + TILE_BYTES;
        const uint32_t bB  = stage + 2u * TILE_BYTES + (uint32_t)(wn * 64 + lrow) * 128u;

#pragma unroll
        for (int ks = 0; ks < 4; ks++) {
            const uint32_t csw = ((uint32_t)(ks * 32 + lcolb)) ^ lxor;
            uint32_t br[4][4];
#pragma unroll
            for (int ng = 0; ng < 4; ng++)
                LDSM4(br[ng], bB + (uint32_t)(ng * 16 * 128) + csw);
#pragma unroll
            for (int mf = 0; mf < 4; mf++) {
                uint32_t af[4];
                LDSM4(af, aHB + (uint32_t)(mf * 16 * 128) + csw);
#pragma unroll
                for (int ng = 0; ng < 4; ng++) {
                    MMA16816(acc[mf][2 * ng],     af, br[ng][0], br[ng][2]);
                    MMA16816(acc[mf][2 * ng + 1], af, br[ng][1], br[ng][3]);
                }
            }
#pragma unroll
            for (int mf = 0; mf < 4; mf++) {
                uint32_t af[4];
                LDSM4(af, aLB + (uint32_t)(mf * 16 * 128) + csw);
#pragma unroll
                for (int ng = 0; ng < 4; ng++) {
                    MMA16816(acc[mf][2 * ng],     af, br[ng][0], br[ng][2]);
                    MMA16816(acc[mf][2 * ng + 1], af, br[ng][1], br[ng][3]);
                }
            }
        }
        __syncthreads();
        if (kc + 2 < 4)
            load_chunk(stage, iBase, jBase, kc + 2, tid);
    }

    // ---------------- mining epilogue ----------------
    const int groupId = lane >> 2;
    const int tid4 = lane & 3;
    const float INFV = __int_as_float(0x7F800000);

    float rmin[4][2];    // [mf][rowhalf]
    float cmin[8][2];    // [nf][colparity]
#pragma unroll
    for (int mf = 0; mf < 4; mf++) { rmin[mf][0] = INFV; rmin[mf][1] = INFV; }
#pragma unroll
    for (int nf = 0; nf < 8; nf++) { cmin[nf][0] = INFV; cmin[nf][1] = INFV; }

#pragma unroll
    for (int mf = 0; mf < 4; mf++) {
#pragma unroll
        for (int nf = 0; nf < 8; nf++) {
#pragma unroll
            for (int r = 0; r < 4; r++) {
                const int row_l = wm * 64 + mf * 16 + groupId + (r >> 1) * 8;
                const int col_l = wn * 64 + nf * 8 + tid4 * 2 + (r & 1);
                const float dot = acc[mf][nf][r];
                float d2 = fmaxf(fmaf(dot, -2.0f, s_sqi[row_l]) + s_sqj[col_l], 0.0f);
                if (row_l == col_l) {
                    s_diag[row_l] = d2;
                } else {
                    rmin[mf][r >> 1] = fminf(rmin[mf][r >> 1], d2);
                    cmin[nf][r & 1]  = fminf(cmin[nf][r & 1], d2);
                }
            }
        }
    }

    // row reduce over tid4 (lanes sharing rows)
#pragma unroll
    for (int mf = 0; mf < 4; mf++) {
#pragma unroll
        for (int h = 0; h < 2; h++) {
            float v = rmin[mf][h];
            v = fminf(v, __shfl_xor_sync(0xFFFFFFFFu, v, 1));
            v = fminf(v, __shfl_xor_sync(0xFFFFFFFFu, v, 2));
            if (tid4 == 0)
                atomicMin(&s_rowmin[wm * 64 + mf * 16 + groupId + 8 * h], __float_as_int(v));
        }
    }
    // col reduce over groupId (lanes sharing cols)
#pragma unroll
    for (int nf = 0; nf < 8; nf++) {
#pragma unroll
        for (int par = 0; par < 2; par++) {
            float v = cmin[nf][par];
            v = fminf(v, __shfl_xor_sync(0xFFFFFFFFu, v, 4));
            v = fminf(v, __shfl_xor_sync(0xFFFFFFFFu, v, 8));
            v = fminf(v, __shfl_xor_sync(0xFFFFFFFFu, v, 16));
            if (groupId == 0)
                atomicMin(&s_colmin[wn * 64 + nf * 8 + tid4 * 2 + par], __float_as_int(v));
        }
    }
    __syncthreads();

    if (tid < 128) {
        const int row = iBase + tid;
        atomicMin(reinterpret_cast<int*>(&g_hn2[row]), s_rowmin[tid]);
        if (!dtile) {
            const int col = jBase + tid;
            atomicMin(reinterpret_cast<int*>(&g_hn2[col]), s_colmin[tid]);
            const int db = __float_as_int(s_diag[tid]);
            atomicMax(reinterpret_cast<int*>(&g_hp2[row]), db);
            atomicMax(reinterpret_cast<int*>(&g_hp2[col]), db);
        }
    }
}

// ---------------------------------------------------------------------------
// Kernel 2: final scalar = dr + t_loss + mse. Single block, deterministic.
// ---------------------------------------------------------------------------
__global__ void final_kernel(const float* __restrict__ gt,
                             const float* __restrict__ s0,
                             const float* __restrict__ s1,
                             const float* __restrict__ s2,
                             float* __restrict__ out) {
    __shared__ float red[256];
    const int tid = threadIdx.x;

    float tsum = 0.0f;
    for (int i = tid; i < NROWS; i += 256) {
        float hp = sqrtf(fmaxf(g_hp2[i], 0.0f));
        float hn = sqrtf(fmaxf(g_hn2[i], 0.0f));
        tsum += fmaxf(hp - hn + MARGIN, 0.0f);
    }

    float msum = 0.0f;
    if (tid < BQ) {
        float g = gt[tid];
        float a = s0[tid] - g, b = s1[tid] - g, c = s2[tid] - g;
        msum = a * a + b * b + c * c;
    }

    float dsum = (tid < NDRBLK) ? g_dpart[tid] : 0.0f;

    float vals[3] = {tsum, msum, dsum};
    float res[3];
#pragma unroll
    for (int v = 0; v < 3; v++) {
        red[tid] = vals[v];
        __syncthreads();
        for (int st = 128; st > 0; st >>= 1) {
            if (tid < st) red[tid] += red[tid + st];
            __syncthreads();
        }
        res[v] = red[0];
        __syncthreads();
    }

    if (tid == 0) {
        float t_loss = res[0] / (float)NROWS;
        float mse    = res[1] / (float)(BQ * 3);
        float dr     = res[2] / (float)DDIM;
        out[0] = dr + t_loss + mse;
    }
}

// ---------------------------------------------------------------------------
extern "C" void kernel_launch(void* const* d_in, const int* in_sizes, int n_in,
                              void* d_out, int out_size) {
    const float* feat = (const float*)d_in[0];
    const float* gt   = (const float*)d_in[1];
    const float* s0   = (const float*)d_in[2];
    const float* s1   = (const float*)d_in[3];
    const float* s2   = (const float*)d_in[4];
    const float* e0   = (const float*)d_in[5];
    const float* e1   = (const float*)d_in[6];
    const float* l0   = (const float*)d_in[7];
    const float* l1   = (const float*)d_in[8];
    float* out = (float*)d_out;

    cudaFuncSetAttribute(pair_mma_kernel,
                         cudaFuncAttributeMaxDynamicSharedMemorySize, SMEM_DYN);

    prep_kernel<<<NPREPBLK + NDRBLK, 256>>>(feat, e0, e1, l0, l1);
    pair_mma_kernel<<<NPAIRTILES, NTHREADS, SMEM_DYN>>>();
    final_kernel<<<1, 256>>>(gt, s0, s1, s2, out);
}

// round 6
// speedup vs baseline: 10.4104x; 1.4733x over previous
#include <cuda_runtime.h>
#include <cuda_fp16.h>
#include <math.h>
#include <stdint.h>

// ---------------- problem constants ----------------
#define NROWS 8192      // b*n
#define CDIM  256
#define NTILES 64
#define NPAIRTILES 2080 // NTILES*(NTILES+1)/2
#define BQ    64
#define DDIM  65536
#define MARGIN 0.3f
#define FLTMAX_BITS 0x7F7FFFFF

#define NTHREADS 128               // 4 warps, each 64x64
#define TILE_BYTES 16384           // 128 rows x 128B (64 fp16 cols)
#define STAGE_BYTES (2 * TILE_BYTES)  // A, B
#define SMEM_DYN (2 * STAGE_BYTES + 1024)
#define NDRBLK 64
#define NPREPBLK 1024              // 8 rows per block (8 warps x 256 thr)

// ---------------- device globals (no allocs allowed) ----------------
__device__ __align__(128) __half g_P[(size_t)NROWS * CDIM];
__device__ float g_sq[NROWS];
__device__ float g_hp2[NROWS];
__device__ float g_hn2[NROWS];
__device__ float g_dpart[NDRBLK];

// ---------------- PTX helpers (baseline sm_80-class only) ----------------
__device__ __forceinline__ uint32_t smem_u32(const void* p) {
    uint32_t a;
    asm("{ .reg .u64 t; cvta.to.shared.u64 t, %1; cvt.u32.u64 %0, t; }" : "=r"(a) : "l"(p));
    return a;
}

#define CP_ASYNC16(dst, src) \
    asm volatile("cp.async.cg.shared.global [%0], [%1], 16;" :: "r"(dst), "l"(src) : "memory")
#define CP_COMMIT() asm volatile("cp.async.commit_group;" ::: "memory")

#define LDSM4(r, addr) \
    asm volatile("ldmatrix.sync.aligned.m8n8.x4.shared.b16 {%0,%1,%2,%3}, [%4];" \
        : "=r"((r)[0]), "=r"((r)[1]), "=r"((r)[2]), "=r"((r)[3]) : "r"(addr))

#define MMA16816(d, a, b0, b1) \
    asm volatile("mma.sync.aligned.m16n8k16.row.col.f32.f16.f16.f32 " \
        "{%0,%1,%2,%3}, {%4,%5,%6,%7}, {%8,%9}, {%0,%1,%2,%3};" \
        : "+f"((d)[0]), "+f"((d)[1]), "+f"((d)[2]), "+f"((d)[3]) \
        : "r"((a)[0]), "r"((a)[1]), "r"((a)[2]), "r"((a)[3]), "r"(b0), "r"(b1))

// ---------------------------------------------------------------------------
// Kernel 0 (fused): blocks [0,1024): fp16 convert + row norms (of the ROUNDED
// values, so d2 is self-consistent) + hp/hn reset, one warp per row.
// Blocks [1024,1088): dr (L1) partial sums.
// ---------------------------------------------------------------------------
__global__ void prep_kernel(const float* __restrict__ x,
                            const float* __restrict__ e0,
                            const float* __restrict__ e1,
                            const float* __restrict__ l0,
                            const float* __restrict__ l1) {
    const int tid = threadIdx.x;
    if (blockIdx.x < NPREPBLK) {
        const int wid = tid >> 5, lane = tid & 31;
        const int row = blockIdx.x * 8 + wid;
        const float4* xr = reinterpret_cast<const float4*>(x + (size_t)row * CDIM);
        float4 v0 = xr[lane * 2 + 0];
        float4 v1 = xr[lane * 2 + 1];
        float a[8] = {v0.x, v0.y, v0.z, v0.w, v1.x, v1.y, v1.z, v1.w};
        float s = 0.0f;
        unsigned hb[8];
#pragma unroll
        for (int i = 0; i < 8; i++) {
            __half h = __float2half_rn(a[i]);
            hb[i] = (unsigned)__half_as_ushort(h);
            float r = __half2float(h);
            s = fmaf(r, r, s);
        }
        uint4 ph = make_uint4(hb[0] | (hb[1] << 16), hb[2] | (hb[3] << 16),
                              hb[4] | (hb[5] << 16), hb[6] | (hb[7] << 16));
        *reinterpret_cast<uint4*>(&g_P[(size_t)row * CDIM + lane * 8]) = ph;
#pragma unroll
        for (int off = 16; off > 0; off >>= 1)
            s += __shfl_xor_sync(0xFFFFFFFFu, s, off);
        if (lane == 0) {
            g_sq[row]  = s;
            g_hp2[row] = 0.0f;
            g_hn2[row] = __int_as_float(FLTMAX_BITS);
        }
    } else {
        __shared__ float red[256];
        const int b = blockIdx.x - NPREPBLK;
        const int base = b * (DDIM / NDRBLK);
        float s = 0.0f;
#pragma unroll
        for (int k = 0; k < DDIM / NDRBLK / 256; k++) {
            int i = base + k * 256 + tid;
            s += fabsf(e0[i] - l0[i]) + fabsf(e1[i] - l1[i]);
        }
        red[tid] = s;
        __syncthreads();
        for (int st = 128; st > 0; st >>= 1) {
            if (tid < st) red[tid] += red[tid + st];
            __syncthreads();
        }
        if (tid == 0) g_dpart[b] = red[0];
    }
}

// ---------------------------------------------------------------------------
// Load one 64-col chunk kc into a stage: A (rows iBase..), B (rows jBase..).
// 128 threads x 16 cp.async x 16B, SW128 swizzle.
// ---------------------------------------------------------------------------
__device__ __forceinline__ void load_chunk(uint32_t stage, int iBase, int jBase,
                                           int kc, int tid) {
    const int cu = tid & 7;          // 16B column unit
    const int r0 = tid >> 3;         // 0..15
    const uint32_t colsw = ((uint32_t)(cu * 16)) ^ (((uint32_t)(r0 & 7)) << 4);
    const int ecol = kc * 64 + cu * 8;
#pragma unroll
    for (int i = 0; i < 8; i++) {
        const int row = r0 + 16 * i;
        const uint32_t dst = stage + (uint32_t)row * 128u + colsw;
        CP_ASYNC16(dst,              &g_P[(size_t)(iBase + row) * CDIM + ecol]); // A
        CP_ASYNC16(dst + TILE_BYTES, &g_P[(size_t)(jBase + row) * CDIM + ecol]); // B
    }
    CP_COMMIT();
}

// ---------------------------------------------------------------------------
// Kernel 1: warp-MMA fused Gram + mining, one 128x128 tile (it<=jt) per CTA.
// Single fp16 term, fp32 accum. 4 warps, 64x64 each.
// ---------------------------------------------------------------------------
__global__ void __launch_bounds__(NTHREADS) pair_mma_kernel() {
    extern __shared__ __align__(16) char dsm[];
    __shared__ float s_sqi[128], s_sqj[128], s_diag[128];
    __shared__ int s_rowmin[128], s_colmin[128];

    const int tid = threadIdx.x;
    const int wid = tid >> 5;
    const int lane = tid & 31;
    const int wm = wid & 1;          // 2 warps along m
    const int wn = wid >> 1;         // 2 warps along n
    const int lrow = lane & 15;
    const int lcolb = (lane >> 4) * 16;
    const uint32_t lxor = ((uint32_t)(lrow & 7)) << 4;

    // triangular tile decode
    int t = blockIdx.x;
    int it = (int)floorf((129.0f - sqrtf(129.0f * 129.0f - 8.0f * (float)t)) * 0.5f);
    while (it > 0 && (it * (129 - it)) / 2 > t) it--;
    while (((it + 1) * (129 - (it + 1))) / 2 <= t) it++;
    const int jt = it + (t - (it * (129 - it)) / 2);
    const int iBase = it * 128;
    const int jBase = jt * 128;
    const bool dtile = (it == jt);

    const uint32_t sb = smem_u32(dsm);
    const uint32_t stage0 = (sb + 1023u) & ~1023u;
    const uint32_t stage1 = stage0 + STAGE_BYTES;

    if (tid < 128) {
        s_sqi[tid] = g_sq[iBase + tid];
        s_sqj[tid] = g_sq[jBase + tid];
        s_rowmin[tid] = FLTMAX_BITS;
        s_colmin[tid] = FLTMAX_BITS;
    }

    float acc[4][8][4];
#pragma unroll
    for (int mf = 0; mf < 4; mf++)
#pragma unroll
        for (int nf = 0; nf < 8; nf++)
#pragma unroll
            for (int r = 0; r < 4; r++) acc[mf][nf][r] = 0.0f;

    load_chunk(stage0, iBase, jBase, 0, tid);
    load_chunk(stage1, iBase, jBase, 1, tid);

#pragma unroll 1
    for (int kc = 0; kc < 4; kc++) {
        const uint32_t stage = (kc & 1) ? stage1 : stage0;
        if (kc < 3) asm volatile("cp.async.wait_group 1;" ::: "memory");
        else        asm volatile("cp.async.wait_group 0;" ::: "memory");
        __syncthreads();

        const uint32_t aB = stage + (uint32_t)(wm * 64 + lrow) * 128u;
        const uint32_t bB = stage + (uint32_t)TILE_BYTES
                          + (uint32_t)(wn * 64 + lrow) * 128u;

#pragma unroll
        for (int ks = 0; ks < 4; ks++) {
            const uint32_t csw = ((uint32_t)(ks * 32 + lcolb)) ^ lxor;
            uint32_t br[4][4];
#pragma unroll
            for (int ng = 0; ng < 4; ng++)
                LDSM4(br[ng], bB + (uint32_t)(ng * 16 * 128) + csw);
#pragma unroll
            for (int mf = 0; mf < 4; mf++) {
                uint32_t af[4];
                LDSM4(af, aB + (uint32_t)(mf * 16 * 128) + csw);
#pragma unroll
                for (int ng = 0; ng < 4; ng++) {
                    MMA16816(acc[mf][2 * ng],     af, br[ng][0], br[ng][2]);
                    MMA16816(acc[mf][2 * ng + 1], af, br[ng][1], br[ng][3]);
                }
            }
        }
        __syncthreads();
        if (kc + 2 < 4)
            load_chunk(stage, iBase, jBase, kc + 2, tid);
    }

    // ---------------- mining epilogue ----------------
    const int groupId = lane >> 2;
    const int tid4 = lane & 3;
    const float INFV = __int_as_float(0x7F800000);

    float rmin[4][2];    // [mf][rowhalf]
    float cmin[8][2];    // [nf][colparity]
#pragma unroll
    for (int mf = 0; mf < 4; mf++) { rmin[mf][0] = INFV; rmin[mf][1] = INFV; }
#pragma unroll
    for (int nf = 0; nf < 8; nf++) { cmin[nf][0] = INFV; cmin[nf][1] = INFV; }

#pragma unroll
    for (int mf = 0; mf < 4; mf++) {
#pragma unroll
        for (int nf = 0; nf < 8; nf++) {
#pragma unroll
            for (int r = 0; r < 4; r++) {
                const int row_l = wm * 64 + mf * 16 + groupId + (r >> 1) * 8;
                const int col_l = wn * 64 + nf * 8 + tid4 * 2 + (r & 1);
                const float dot = acc[mf][nf][r];
                float d2 = fmaxf(fmaf(dot, -2.0f, s_sqi[row_l]) + s_sqj[col_l], 0.0f);
                if (row_l == col_l) {
                    s_diag[row_l] = d2;
                } else {
                    rmin[mf][r >> 1] = fminf(rmin[mf][r >> 1], d2);
                    cmin[nf][r & 1]  = fminf(cmin[nf][r & 1], d2);
                }
            }
        }
    }

    // row reduce over tid4 (lanes sharing rows)
#pragma unroll
    for (int mf = 0; mf < 4; mf++) {
#pragma unroll
        for (int h = 0; h < 2; h++) {
            float v = rmin[mf][h];
            v = fminf(v, __shfl_xor_sync(0xFFFFFFFFu, v, 1));
            v = fminf(v, __shfl_xor_sync(0xFFFFFFFFu, v, 2));
            if (tid4 == 0)
                atomicMin(&s_rowmin[wm * 64 + mf * 16 + groupId + 8 * h], __float_as_int(v));
        }
    }
    // col reduce over groupId (lanes sharing cols)
#pragma unroll
    for (int nf = 0; nf < 8; nf++) {
#pragma unroll
        for (int par = 0; par < 2; par++) {
            float v = cmin[nf][par];
            v = fminf(v, __shfl_xor_sync(0xFFFFFFFFu, v, 4));
            v = fminf(v, __shfl_xor_sync(0xFFFFFFFFu, v, 8));
            v = fminf(v, __shfl_xor_sync(0xFFFFFFFFu, v, 16));
            if (groupId == 0)
                atomicMin(&s_colmin[wn * 64 + nf * 8 + tid4 * 2 + par], __float_as_int(v));
        }
    }
    __syncthreads();

    if (tid < 128) {
        const int row = iBase + tid;
        atomicMin(reinterpret_cast<int*>(&g_hn2[row]), s_rowmin[tid]);
        if (!dtile) {
            const int col = jBase + tid;
            atomicMin(reinterpret_cast<int*>(&g_hn2[col]), s_colmin[tid]);
            const int db = __float_as_int(s_diag[tid]);
            atomicMax(reinterpret_cast<int*>(&g_hp2[row]), db);
            atomicMax(reinterpret_cast<int*>(&g_hp2[col]), db);
        }
    }
}

// ---------------------------------------------------------------------------
// Kernel 2: final scalar = dr + t_loss + mse. Single block, deterministic.
// ---------------------------------------------------------------------------
__global__ void final_kernel(const float* __restrict__ gt,
                             const float* __restrict__ s0,
                             const float* __restrict__ s1,
                             const float* __restrict__ s2,
                             float* __restrict__ out) {
    __shared__ float red[256];
    const int tid = threadIdx.x;

    float tsum = 0.0f;
    for (int i = tid; i < NROWS; i += 256) {
        float hp = sqrtf(fmaxf(g_hp2[i], 0.0f));
        float hn = sqrtf(fmaxf(g_hn2[i], 0.0f));
        tsum += fmaxf(hp - hn + MARGIN, 0.0f);
    }

    float msum = 0.0f;
    if (tid < BQ) {
        float g = gt[tid];
        float a = s0[tid] - g, b = s1[tid] - g, c = s2[tid] - g;
        msum = a * a + b * b + c * c;
    }

    float dsum = (tid < NDRBLK) ? g_dpart[tid] : 0.0f;

    float vals[3] = {tsum, msum, dsum};
    float res[3];
#pragma unroll
    for (int v = 0; v < 3; v++) {
        red[tid] = vals[v];
        __syncthreads();
        for (int st = 128; st > 0; st >>= 1) {
            if (tid < st) red[tid] += red[tid + st];
            __syncthreads();
        }
        res[v] = red[0];
        __syncthreads();
    }

    if (tid == 0) {
        float t_loss = res[0] / (float)NROWS;
        float mse    = res[1] / (float)(BQ * 3);
        float dr     = res[2] / (float)DDIM;
        out[0] = dr + t_loss + mse;
    }
}

// ---------------------------------------------------------------------------
extern "C" void kernel_launch(void* const* d_in, const int* in_sizes, int n_in,
                              void* d_out, int out_size) {
    const float* feat = (const float*)d_in[0];
    const float* gt   = (const float*)d_in[1];
    const float* s0   = (const float*)d_in[2];
    const float* s1   = (const float*)d_in[3];
    const float* s2   = (const float*)d_in[4];
    const float* e0   = (const float*)d_in[5];
    const float* e1   = (const float*)d_in[6];
    const float* l0   = (const float*)d_in[7];
    const float* l1   = (const float*)d_in[8];
    float* out = (float*)d_out;

    cudaFuncSetAttribute(pair_mma_kernel,
                         cudaFuncAttributeMaxDynamicSharedMemorySize, SMEM_DYN);

    prep_kernel<<<NPREPBLK + NDRBLK, 256>>>(feat, e0, e1, l0, l1);
    pair_mma_kernel<<<NPAIRTILES, NTHREADS, SMEM_DYN>>>();
    final_kernel<<<1, 256>>>(gt, s0, s1, s2, out);
}